// round 11
// baseline (speedup 1.0000x reference)
#include <cuda_runtime.h>
#include <cuda_bf16.h>
#include <stdint.h>

#define BB      8192
#define LBITS   128
#define NP      4096
#define MARGIN  64
#define NPACK   128                // blocks 1..128: stream/pack + 1 pair/warp
#define GRID    (1 + NPACK)       // 129 blocks, single wave
#define NT      1024

// ---------------- device scratch (static, zero-init at load) -----------------
__device__ double       g_quant_part[NPACK];
__device__ int          g_col_part[NPACK][LBITS];
__device__ unsigned     g_pos_part[NPACK];
__device__ uint4        g_dots4[BB / 4];   // per row: (dot0+128)|(dot1+128)<<16
__device__ unsigned     g_dots_done;       // monotonic: +1 per pack block
__device__ unsigned     g_pos_done;        // monotonic: +1 per pack block
__device__ unsigned     g_epoch;           // monotonic: neg-block replay ticket

__global__ void __launch_bounds__(NT, 1)
fused_kernel(const float* __restrict__ bh,
             const float* __restrict__ ch,
             const void*  __restrict__ pos,
             float*       __restrict__ out)
{
    __shared__ unsigned char flags[2 * BB];   // 16 KB   (neg block)
    __shared__ int    s_part[32][129];        // 16.5 KB (pack: per-warp cols;
                                              //          neg: 8x group sums)
    __shared__ int    scanw[NT / 32];
    __shared__ float  s_q[NT / 32];
    __shared__ double s_d[LBITS];
    __shared__ unsigned s_epoch;

    const int tid  = threadIdx.x;
    const int warp = tid >> 5;
    const int lane = tid & 31;
    const int bx   = blockIdx.x;

    if (bx >= 1) {
        // ===== PACK blocks: stream bh+ch, colsums, quant, dots, then 1 pair ==
        const int pb = bx - 1;

        // rows 0 and 1 packed bits (identical in every warp; L2 broadcast)
        float4 r0f = ((const float4*)bh)[lane];
        float4 r1f = ((const float4*)bh)[32 + lane];
        unsigned r00 = __ballot_sync(0xffffffffu, r0f.x < 0.f);
        unsigned r01 = __ballot_sync(0xffffffffu, r0f.y < 0.f);
        unsigned r02 = __ballot_sync(0xffffffffu, r0f.z < 0.f);
        unsigned r03 = __ballot_sync(0xffffffffu, r0f.w < 0.f);
        unsigned r10 = __ballot_sync(0xffffffffu, r1f.x < 0.f);
        unsigned r11 = __ballot_sync(0xffffffffu, r1f.y < 0.f);
        unsigned r12 = __ballot_sync(0xffffffffu, r1f.z < 0.f);
        unsigned r13 = __ballot_sync(0xffffffffu, r1f.w < 0.f);

        float quacc = 0.f;
        int ca0 = 0, ca1 = 0, ca2 = 0, ca3 = 0;
        #pragma unroll
        for (int it = 0; it < 2; ++it) {
            int r = pb * 64 + warp * 2 + it;       // 64 rows per block
            float4 x = ((const float4*)bh)[r * 32 + lane];
            float4 c = ((const float4*)ch)[r * 32 + lane];
            unsigned b0 = __ballot_sync(0xffffffffu, x.x < 0.f);
            unsigned b1 = __ballot_sync(0xffffffffu, x.y < 0.f);
            unsigned b2 = __ballot_sync(0xffffffffu, x.z < 0.f);
            unsigned b3 = __ballot_sync(0xffffffffu, x.w < 0.f);
            int D0 = __popc(b0 ^ r00) + __popc(b1 ^ r01)
                   + __popc(b2 ^ r02) + __popc(b3 ^ r03);
            int D1 = __popc(b0 ^ r10) + __popc(b1 ^ r11)
                   + __popc(b2 ^ r12) + __popc(b3 ^ r13);
            if (lane == 0)
                ((unsigned*)g_dots4)[r] =
                    (unsigned)(LBITS - 2 * D0 + 128)
                  | ((unsigned)(LBITS - 2 * D1 + 128) << 16);
            ca0 += (x.x < 0.f) ? -1 : 1;
            ca1 += (x.y < 0.f) ? -1 : 1;
            ca2 += (x.z < 0.f) ? -1 : 1;
            ca3 += (x.w < 0.f) ? -1 : 1;
            quacc += fabsf(fabsf(c.x) - 1.f) + fabsf(fabsf(c.y) - 1.f)
                   + fabsf(fabsf(c.z) - 1.f) + fabsf(fabsf(c.w) - 1.f);
        }
        // per-warp column partials (consistent lane->column permutation:
        // dots, colsums, sum(m^2) all permutation-invariant). No atomics.
        s_part[warp][4 * lane + 0] = ca0;
        s_part[warp][4 * lane + 1] = ca1;
        s_part[warp][4 * lane + 2] = ca2;
        s_part[warp][4 * lane + 3] = ca3;
        #pragma unroll
        for (int off = 16; off; off >>= 1)
            quacc += __shfl_down_sync(0xffffffffu, quacc, off);
        if (lane == 0) s_q[warp] = quacc;
        __syncthreads();

        // warp 0 publishes pack results, then lane 0 fences + ticks dots
        if (warp == 0) {
            #pragma unroll
            for (int j = 0; j < 4; ++j) {       // lane l owns cols l+32j
                int c = lane + 32 * j;
                int cs = 0;
                #pragma unroll
                for (int w = 0; w < 32; ++w) cs += s_part[w][c];
                g_col_part[pb][c] = cs;
            }
            float qq = s_q[lane];
            #pragma unroll
            for (int off = 16; off; off >>= 1)
                qq += __shfl_down_sync(0xffffffffu, qq, off);
            if (lane == 0) {
                g_quant_part[pb] = (double)qq;
                __threadfence();                       // release dots+partials
                atomicAdd(&g_dots_done, 1u);
            }
        }

        // ---- POS: exactly one pair per warp (pair = pb*32 + warp) ----------
        const int* p32 = (const int*)pos;
        int any = 0;
        for (int i = tid; i < NP; i += NT) any |= (p32[2 * i + 1] != 0);
        const int is32 = __syncthreads_or(any);

        int p = pb * 32 + warp;
        int q = 0, d = 0;
        if (lane == 0) {
            if (is32) { q = p32[2 * p] & (BB - 1); d = p32[2 * p + 1] & (BB - 1); }
            else      { q = p32[4 * p] & (BB - 1); d = p32[4 * p + 2] & (BB - 1); }
        }
        q = __shfl_sync(0xffffffffu, q, 0);
        d = __shfl_sync(0xffffffffu, d, 0);
        float4 a = ((const float4*)bh)[q * 32 + lane];
        float4 b = ((const float4*)bh)[d * 32 + lane];
        int mm = ((a.x < 0.f) != (b.x < 0.f))
               + ((a.y < 0.f) != (b.y < 0.f))
               + ((a.z < 0.f) != (b.z < 0.f))
               + ((a.w < 0.f) != (b.w < 0.f));
        #pragma unroll
        for (int off = 16; off; off >>= 1)
            mm += __shfl_down_sync(0xffffffffu, mm, off);
        unsigned term = 0;
        if (lane == 0) {
            int diff = MARGIN - (LBITS - 2 * mm);      // margin - dot
            if (diff > 0) term = (unsigned)(diff * diff);
            s_q[warp] = __uint_as_float(term);
        }
        __syncthreads();
        if (warp == 0) {
            unsigned bs = __float_as_uint(s_q[lane]);
            #pragma unroll
            for (int off = 16; off; off >>= 1)
                bs += __shfl_down_sync(0xffffffffu, bs, off);
            if (lane == 0) {
                g_pos_part[pb] = bs;
                __threadfence();                       // release
                atomicAdd(&g_pos_done, 1u);
            }
        }
    }
    else {
        // ========== NEG block: prep overlapped; does the final combine =======
        if (tid == 0) s_epoch = atomicAdd(&g_epoch, 1u);
        const int* p32 = (const int*)pos;
        int any = 0;
        for (int i = tid; i < NP; i += NT) any |= (p32[2 * i + 1] != 0);
        const int is32 = __syncthreads_or(any);

        // selection provably confined to rows 0,1: those rows hold
        // >= 2*(BB-1) - 2*NP = 8190 >= NP candidates.
        for (int i = tid; i < (2 * BB) / 4; i += NT) ((int*)flags)[i] = 0;
        __syncthreads();
        for (int p = tid; p < NP; p += NT) {
            int q, d;
            if (is32) { q = p32[2 * p] & (BB - 1); d = p32[2 * p + 1] & (BB - 1); }
            else      { q = p32[4 * p] & (BB - 1); d = p32[4 * p + 2] & (BB - 1); }
            if (q < 2) flags[q * BB + d] = 1;
            if (d < 2) flags[d * BB + q] = 1;
        }
        if (tid == 0) { flags[0] = 1; flags[BB + 1] = 1; }  // diag (0,0),(1,1)
        __syncthreads();

        const int base = tid * 16;
        int cnt = 0;
        #pragma unroll
        for (int i = 0; i < 16; ++i) cnt += flags[base + i] ? 0 : 1;
        // shfl-based block scan (3 barriers)
        int val = cnt;
        #pragma unroll
        for (int off = 1; off < 32; off <<= 1) {
            int n = __shfl_up_sync(0xffffffffu, val, off);
            if (lane >= off) val += n;
        }
        if (lane == 31) scanw[warp] = val;
        __syncthreads();
        if (warp == 0) {
            int t = scanw[lane];
            #pragma unroll
            for (int off = 1; off < 32; off <<= 1) {
                int n = __shfl_up_sync(0xffffffffu, t, off);
                if (lane >= off) t += n;
            }
            scanw[lane] = t;
        }
        __syncthreads();
        int run = ((warp == 0) ? 0 : scanw[warp - 1]) + val - cnt;  // exclusive

        // wait: all pack blocks published dots + partials for THIS replay
        if (tid == 0) {
            unsigned target = (s_epoch + 1u) * NPACK;
            while (*(volatile unsigned*)&g_dots_done < target) { }
        }
        __syncthreads();

        const int row  = base >> 13;
        const int col0 = base & (BB - 1);
        unsigned dw[16];
        #pragma unroll
        for (int j = 0; j < 4; ++j) {
            uint4 w = __ldcg(&g_dots4[(col0 >> 2) + j]);   // L2, no L1 flush
            dw[4 * j + 0] = w.x; dw[4 * j + 1] = w.y;
            dw[4 * j + 2] = w.z; dw[4 * j + 3] = w.w;
        }
        unsigned acc = 0;
        #pragma unroll
        for (int i = 0; i < 16; ++i) {
            if (!flags[base + i]) {
                if (run < NP) {
                    unsigned v = dw[i];
                    int dot = (int)(row ? (v >> 16) : (v & 0xffffu)) - 128;
                    int t = dot + MARGIN;
                    if (t > 0) acc += (unsigned)(t * t);
                }
                run++;
            }
        }
        #pragma unroll
        for (int off = 16; off; off >>= 1)
            acc += __shfl_down_sync(0xffffffffu, acc, off);
        if (lane == 0) s_q[warp] = __uint_as_float(acc);
        __syncthreads();
        unsigned negT = 0;
        if (warp == 0) {
            negT = __float_as_uint(s_q[lane]);
            #pragma unroll
            for (int off = 16; off; off >>= 1)
                negT += __shfl_down_sync(0xffffffffu, negT, off);
        }

        // wait: all pack blocks published their pos partials
        if (tid == 0) {
            unsigned target = (s_epoch + 1u) * NPACK;
            while (*(volatile unsigned*)&g_pos_done < target) { }
        }
        __syncthreads();

        // ---- combine (in this block; no global done ticket) ----
        unsigned posT = 0;
        if (warp == 0) {
            unsigned pv = 0;
            #pragma unroll
            for (int j = 0; j < 4; ++j)
                pv += __ldcg(&g_pos_part[lane + 32 * j]);
            #pragma unroll
            for (int off = 16; off; off >>= 1)
                pv += __shfl_down_sync(0xffffffffu, pv, off);
            posT = pv;                       // valid in lane 0 (== tid 0)
        }
        // colsum: 1024 threads over 128x128 ints, then 8-group smem reduce
        {
            int c = tid & (LBITS - 1);
            int g = tid >> 7;                // 0..7
            int cs = 0;
            #pragma unroll
            for (int k = 0; k < NPACK / 8; ++k)
                cs += __ldcg(&g_col_part[g * (NPACK / 8) + k][c]);
            s_part[g][c] = cs;
        }
        __syncthreads();
        if (tid < LBITS) {
            int cs = 0;
            #pragma unroll
            for (int g = 0; g < 8; ++g) cs += s_part[g][tid];
            double m = (double)cs / (double)BB;
            // fused: 0.1*bal + 0.5*quant share one 128-term tree
            s_d[tid] = 0.1 * m * m
                     + (0.5 / ((double)BB * (double)LBITS))
                       * __ldcg(&g_quant_part[tid]);
        }
        __syncthreads();
        #pragma unroll
        for (int off = 64; off > 0; off >>= 1) {
            if (tid < off) s_d[tid] += s_d[tid + off];
            __syncthreads();
        }
        if (tid == 0) {
            // num_neg = min(~67M, NP) = NP always -> denominator 2*NP
            double sim = (double)(negT + posT) / (double)(NP + NP);
            out[0] = (float)(sim + s_d[0]);
        }
    }
}

// ---------------- launch ------------------------------------------------------
extern "C" void kernel_launch(void* const* d_in, const int* in_sizes, int n_in,
                              void* d_out, int out_size) {
    const float* bh  = (const float*)d_in[0];
    const float* ch  = (const float*)d_in[1];
    const void*  pos = (const void*)d_in[2];
    fused_kernel<<<GRID, NT>>>(bh, ch, pos, (float*)d_out);
}

// round 12
// speedup vs baseline: 1.7727x; 1.7727x over previous
#include <cuda_runtime.h>
#include <cuda_bf16.h>
#include <stdint.h>

#define BB      8192
#define LBITS   128
#define NP      4096
#define MARGIN  64
#define NPOSB   16                 // blocks 1..16: positive pairs
#define NPACK   128                // blocks 17..144: streaming/pack
#define PACK0   (1 + NPOSB)
#define GRID    (1 + NPOSB + NPACK)   // 145 blocks, single wave
#define NT      1024

// ---------------- device scratch (static, zero-init at load) -----------------
__device__ double       g_quant_part[NPACK];
__device__ int          g_col_part[NPACK][LBITS];
__device__ unsigned     g_pos_part[NPOSB];
__device__ uint4        g_dots4[BB / 4];   // per row: (dot0+128)|(dot1+128)<<16
__device__ unsigned     g_dots_done;       // monotonic: +1 per pack block
__device__ unsigned     g_pos_done;        // monotonic: +1 per pos block
__device__ unsigned     g_epoch;           // monotonic: neg-block replay ticket

__global__ void __launch_bounds__(NT, 1)
fused_kernel(const float* __restrict__ bh,
             const float* __restrict__ ch,
             const void*  __restrict__ pos,
             float*       __restrict__ out)
{
    __shared__ unsigned char flags[2 * BB];   // 16 KB   (neg block)
    __shared__ int    s_part[32][129];        // 16.5 KB (pack: per-warp cols;
                                              //          neg: 8x group sums)
    __shared__ int    scanw[NT / 32];
    __shared__ float  s_q[NT / 32];
    __shared__ double s_d[LBITS];
    __shared__ unsigned s_epoch;

    const int tid  = threadIdx.x;
    const int warp = tid >> 5;
    const int lane = tid & 31;
    const int bx   = blockIdx.x;

    if (bx >= PACK0) {
        // ========== PACK blocks: stream bh+ch, colsums, quant, dots vs r0/r1 =
        const int pb = bx - PACK0;

        // rows 0 and 1 packed bits (identical in every warp; L2 broadcast)
        float4 r0f = ((const float4*)bh)[lane];
        float4 r1f = ((const float4*)bh)[32 + lane];
        unsigned r00 = __ballot_sync(0xffffffffu, r0f.x < 0.f);
        unsigned r01 = __ballot_sync(0xffffffffu, r0f.y < 0.f);
        unsigned r02 = __ballot_sync(0xffffffffu, r0f.z < 0.f);
        unsigned r03 = __ballot_sync(0xffffffffu, r0f.w < 0.f);
        unsigned r10 = __ballot_sync(0xffffffffu, r1f.x < 0.f);
        unsigned r11 = __ballot_sync(0xffffffffu, r1f.y < 0.f);
        unsigned r12 = __ballot_sync(0xffffffffu, r1f.z < 0.f);
        unsigned r13 = __ballot_sync(0xffffffffu, r1f.w < 0.f);

        float quacc = 0.f;
        int ca0 = 0, ca1 = 0, ca2 = 0, ca3 = 0;
        #pragma unroll
        for (int it = 0; it < 2; ++it) {
            int r = pb * 64 + warp * 2 + it;       // 64 rows per block
            float4 x = ((const float4*)bh)[r * 32 + lane];
            float4 c = ((const float4*)ch)[r * 32 + lane];
            unsigned b0 = __ballot_sync(0xffffffffu, x.x < 0.f);
            unsigned b1 = __ballot_sync(0xffffffffu, x.y < 0.f);
            unsigned b2 = __ballot_sync(0xffffffffu, x.z < 0.f);
            unsigned b3 = __ballot_sync(0xffffffffu, x.w < 0.f);
            int D0 = __popc(b0 ^ r00) + __popc(b1 ^ r01)
                   + __popc(b2 ^ r02) + __popc(b3 ^ r03);
            int D1 = __popc(b0 ^ r10) + __popc(b1 ^ r11)
                   + __popc(b2 ^ r12) + __popc(b3 ^ r13);
            if (lane == 0)
                ((unsigned*)g_dots4)[r] =
                    (unsigned)(LBITS - 2 * D0 + 128)
                  | ((unsigned)(LBITS - 2 * D1 + 128) << 16);
            ca0 += (x.x < 0.f) ? -1 : 1;
            ca1 += (x.y < 0.f) ? -1 : 1;
            ca2 += (x.z < 0.f) ? -1 : 1;
            ca3 += (x.w < 0.f) ? -1 : 1;
            quacc += fabsf(fabsf(c.x) - 1.f) + fabsf(fabsf(c.y) - 1.f)
                   + fabsf(fabsf(c.z) - 1.f) + fabsf(fabsf(c.w) - 1.f);
        }
        // per-warp column partials (consistent lane->column permutation:
        // dots, colsums, sum(m^2) all permutation-invariant). No atomics.
        s_part[warp][4 * lane + 0] = ca0;
        s_part[warp][4 * lane + 1] = ca1;
        s_part[warp][4 * lane + 2] = ca2;
        s_part[warp][4 * lane + 3] = ca3;
        #pragma unroll
        for (int off = 16; off; off >>= 1)
            quacc += __shfl_down_sync(0xffffffffu, quacc, off);
        if (lane == 0) s_q[warp] = quacc;
        __syncthreads();

        // warp 0 publishes everything, then its lane 0 fences + ticks
        if (warp == 0) {
            #pragma unroll
            for (int j = 0; j < 4; ++j) {       // lane l owns cols l+32j
                int c = lane + 32 * j;
                int cs = 0;
                #pragma unroll
                for (int w = 0; w < 32; ++w) cs += s_part[w][c];
                g_col_part[pb][c] = cs;
            }
            float qq = s_q[lane];
            #pragma unroll
            for (int off = 16; off; off >>= 1)
                qq += __shfl_down_sync(0xffffffffu, qq, off);
            if (lane == 0) {
                g_quant_part[pb] = (double)qq;
                __threadfence();                       // release dots+partials
                atomicAdd(&g_dots_done, 1u);
            }
        }
    }
    else if (bx >= 1) {
        // ========== POS blocks: float sign dots, 4 pairs per reduction =======
        const int* p32 = (const int*)pos;

        // layout-oblivious prefetch: both interpretations of this warp's 8
        // pairs load BEFORE the detect reduction (no detect->gather chain)
        int p0 = (bx - 1) * 256 + warp * 8;     // 256 pairs/block, 8/warp
        int qa = 0, da = 0, qb = 0, db = 0;
        if (lane < 8) {
            int p = p0 + lane;
            qa = p32[2 * p];  da = p32[2 * p + 1];    // int32 view
            qb = p32[4 * p];  db = p32[4 * p + 2];    // int64 view (lo words)
        }
        int any = 0;
        for (int i = tid; i < NP; i += NT) any |= (p32[2 * i + 1] != 0);
        const int is32 = __syncthreads_or(any);
        int qv = (is32 ? qa : qb) & (BB - 1);
        int dv = (is32 ? da : db) & (BB - 1);

        unsigned acc = 0;
        #pragma unroll
        for (int g = 0; g < 2; ++g) {
            float4 av[4], bv[4];
            #pragma unroll
            for (int j = 0; j < 4; ++j) {
                int q = __shfl_sync(0xffffffffu, qv, 4 * g + j);
                int d = __shfl_sync(0xffffffffu, dv, 4 * g + j);
                av[j] = ((const float4*)bh)[q * 32 + lane];
                bv[j] = ((const float4*)bh)[d * 32 + lane];
            }
            unsigned packed = 0;
            #pragma unroll
            for (int j = 0; j < 4; ++j) {
                unsigned mm = ((av[j].x < 0.f) != (bv[j].x < 0.f))
                            + ((av[j].y < 0.f) != (bv[j].y < 0.f))
                            + ((av[j].z < 0.f) != (bv[j].z < 0.f))
                            + ((av[j].w < 0.f) != (bv[j].w < 0.f));
                packed |= mm << (8 * j);     // per-pair sum <= 128: no carry
            }
            #pragma unroll
            for (int off = 16; off; off >>= 1)
                packed += __shfl_down_sync(0xffffffffu, packed, off);
            if (lane == 0) {
                #pragma unroll
                for (int j = 0; j < 4; ++j) {
                    int mm = (int)((packed >> (8 * j)) & 0xffu);
                    int diff = MARGIN - (LBITS - 2 * mm);   // margin - dot
                    if (diff > 0) acc += (unsigned)(diff * diff);
                }
            }
        }
        if (lane == 0) s_q[warp] = __uint_as_float(acc);
        __syncthreads();
        if (warp == 0) {
            unsigned bs = __float_as_uint(s_q[lane]);
            #pragma unroll
            for (int off = 16; off; off >>= 1)
                bs += __shfl_down_sync(0xffffffffu, bs, off);
            if (lane == 0) {
                g_pos_part[bx - 1] = bs;
                __threadfence();                       // release
                atomicAdd(&g_pos_done, 1u);
            }
        }
    }
    else {
        // ========== NEG block: prep overlapped; does the final combine =======
        if (tid == 0) s_epoch = atomicAdd(&g_epoch, 1u);
        const int* p32 = (const int*)pos;
        int any = 0;
        for (int i = tid; i < NP; i += NT) any |= (p32[2 * i + 1] != 0);
        const int is32 = __syncthreads_or(any);

        // selection provably confined to rows 0,1: those rows hold
        // >= 2*(BB-1) - 2*NP = 8190 >= NP candidates.
        for (int i = tid; i < (2 * BB) / 4; i += NT) ((int*)flags)[i] = 0;
        __syncthreads();
        for (int p = tid; p < NP; p += NT) {
            int q, d;
            if (is32) { q = p32[2 * p] & (BB - 1); d = p32[2 * p + 1] & (BB - 1); }
            else      { q = p32[4 * p] & (BB - 1); d = p32[4 * p + 2] & (BB - 1); }
            if (q < 2) flags[q * BB + d] = 1;
            if (d < 2) flags[d * BB + q] = 1;
        }
        if (tid == 0) { flags[0] = 1; flags[BB + 1] = 1; }  // diag (0,0),(1,1)
        __syncthreads();

        const int base = tid * 16;
        int cnt = 0;
        #pragma unroll
        for (int i = 0; i < 16; ++i) cnt += flags[base + i] ? 0 : 1;
        // shfl-based block scan (3 barriers)
        int val = cnt;
        #pragma unroll
        for (int off = 1; off < 32; off <<= 1) {
            int n = __shfl_up_sync(0xffffffffu, val, off);
            if (lane >= off) val += n;
        }
        if (lane == 31) scanw[warp] = val;
        __syncthreads();
        if (warp == 0) {
            int t = scanw[lane];
            #pragma unroll
            for (int off = 1; off < 32; off <<= 1) {
                int n = __shfl_up_sync(0xffffffffu, t, off);
                if (lane >= off) t += n;
            }
            scanw[lane] = t;
        }
        __syncthreads();
        int run = ((warp == 0) ? 0 : scanw[warp - 1]) + val - cnt;  // exclusive

        // wait: all pack blocks published dots + partials for THIS replay
        if (tid == 0) {
            unsigned target = (s_epoch + 1u) * NPACK;
            while (*(volatile unsigned*)&g_dots_done < target) { }
        }
        __syncthreads();

        const int row  = base >> 13;
        const int col0 = base & (BB - 1);
        unsigned dw[16];
        #pragma unroll
        for (int j = 0; j < 4; ++j) {
            uint4 w = __ldcg(&g_dots4[(col0 >> 2) + j]);   // L2, no L1 flush
            dw[4 * j + 0] = w.x; dw[4 * j + 1] = w.y;
            dw[4 * j + 2] = w.z; dw[4 * j + 3] = w.w;
        }
        unsigned acc = 0;
        #pragma unroll
        for (int i = 0; i < 16; ++i) {
            if (!flags[base + i]) {
                if (run < NP) {
                    unsigned v = dw[i];
                    int dot = (int)(row ? (v >> 16) : (v & 0xffffu)) - 128;
                    int t = dot + MARGIN;
                    if (t > 0) acc += (unsigned)(t * t);
                }
                run++;
            }
        }
        #pragma unroll
        for (int off = 16; off; off >>= 1)
            acc += __shfl_down_sync(0xffffffffu, acc, off);
        if (lane == 0) s_q[warp] = __uint_as_float(acc);
        __syncthreads();
        unsigned negT = 0;
        if (warp == 0) {
            negT = __float_as_uint(s_q[lane]);
            #pragma unroll
            for (int off = 16; off; off >>= 1)
                negT += __shfl_down_sync(0xffffffffu, negT, off);
        }

        // wait: all pos blocks published
        if (tid == 0) {
            unsigned target = (s_epoch + 1u) * NPOSB;
            while (*(volatile unsigned*)&g_pos_done < target) { }
        }
        __syncthreads();

        // ---- combine (in this block; no global done ticket) ----
        unsigned posT = 0;
        if (warp == 0) {
            unsigned pv = (lane < NPOSB) ? __ldcg(&g_pos_part[lane]) : 0u;
            #pragma unroll
            for (int off = 16; off; off >>= 1)
                pv += __shfl_down_sync(0xffffffffu, pv, off);
            posT = pv;                       // valid in lane 0 (== tid 0)
        }
        // colsum: 1024 threads over 128x128 ints, then 8-group smem reduce
        {
            int c = tid & (LBITS - 1);
            int g = tid >> 7;                // 0..7
            int cs = 0;
            #pragma unroll
            for (int k = 0; k < NPACK / 8; ++k)
                cs += __ldcg(&g_col_part[g * (NPACK / 8) + k][c]);
            s_part[g][c] = cs;
        }
        __syncthreads();
        if (tid < LBITS) {
            int cs = 0;
            #pragma unroll
            for (int g = 0; g < 8; ++g) cs += s_part[g][tid];
            double m = (double)cs / (double)BB;
            // fused: 0.1*bal + 0.5*quant share one 128-term tree
            s_d[tid] = 0.1 * m * m
                     + (0.5 / ((double)BB * (double)LBITS))
                       * __ldcg(&g_quant_part[tid]);
        }
        __syncthreads();
        #pragma unroll
        for (int off = 64; off > 0; off >>= 1) {
            if (tid < off) s_d[tid] += s_d[tid + off];
            __syncthreads();
        }
        if (tid == 0) {
            // num_neg = min(~67M, NP) = NP always -> denominator 2*NP
            double sim = (double)(negT + posT) / (double)(NP + NP);
            out[0] = (float)(sim + s_d[0]);
        }
    }
}

// ---------------- launch ------------------------------------------------------
extern "C" void kernel_launch(void* const* d_in, const int* in_sizes, int n_in,
                              void* d_out, int out_size) {
    const float* bh  = (const float*)d_in[0];
    const float* ch  = (const float*)d_in[1];
    const void*  pos = (const void*)d_in[2];
    fused_kernel<<<GRID, NT>>>(bh, ch, pos, (float*)d_out);
}